// round 1
// baseline (speedup 1.0000x reference)
#include <cuda_runtime.h>
#include <math.h>

#define D 1024
#define CCLS 16
#define NB 64
#define TB (D/NB)
#define REGC 0.1f

// ---------------- scratch (device globals; no allocs allowed) ----------------
__device__ float g_sigma[(size_t)CCLS*D*D];   // sigma -> Cholesky L (lower)
__device__ float g_W[(size_t)CCLS*D*D];       // I -> L^-1 -> inv(sigma)
__device__ float g_Lm[(size_t)D*D];           // prior Cholesky factor
__device__ float g_base[(size_t)D*D];         // L L^T + kap m m^T
__device__ float g_mu[CCLS*D];
__device__ float g_sums[CCLS*D];
__device__ float g_v[CCLS*D];                 // W_c mu_c
__device__ int   g_counts[CCLS];
__device__ int   g_offsets[CCLS+1];
__device__ int   g_perm[8192];
__device__ float g_kap;
__device__ float g_kapNj[CCLS];
__device__ float g_invden[CCLS];
__device__ float g_s1[CCLS], g_mn[CCLS];
__device__ float g_A[8192*CCLS], g_B1[8192*CCLS], g_B2[8192*CCLS], g_qn[8192];

// ---------------- stats ----------------
__global__ void k_zero() { if (threadIdx.x < CCLS) g_counts[threadIdx.x] = 0; }

__global__ void k_count(const int* __restrict__ y, int N) {
    int n = blockIdx.x * 256 + threadIdx.x;
    if (n < N) atomicAdd(&g_counts[y[n]], 1);
}

__global__ void k_prep(const float* __restrict__ kappa, const float* __restrict__ nu) {
    if (threadIdx.x == 0) {
        float kap = fabsf(kappa[0]) + 1e-6f;
        float nup = fmaxf(nu[0], (float)(D - 1) + 1e-6f);
        g_kap = kap;
        int off = 0;
        for (int c = 0; c < CCLS; c++) { g_offsets[c] = off; off += g_counts[c]; }
        g_offsets[CCLS] = off;
        for (int c = 0; c < CCLS; c++) {
            float Nj = (float)g_counts[c];
            g_kapNj[c]  = kap + Nj;
            g_invden[c] = 1.0f / (nup + Nj + (float)D + 2.0f);
        }
    }
}

// deterministic stable scatter: rank of n among same-class indices < n
__global__ void k_scatter(const int* __restrict__ y, int N) {
    int n = blockIdx.x * 256 + threadIdx.x;
    if (n >= N) return;
    int c = y[n], r = 0;
    for (int i = 0; i < n; i++) r += (y[i] == c);
    g_perm[g_offsets[c] + r] = n;
}

__global__ void k_sums(const float* __restrict__ X) {
    int c = blockIdx.x;
    int j = blockIdx.y * 256 + threadIdx.x;
    int o = g_offsets[c], e = g_offsets[c + 1];
    float s = 0.f;
    for (int k = o; k < e; k++) s += X[(size_t)g_perm[k] * D + j];
    g_sums[c * D + j] = s;
}

__global__ void k_mu(const float* __restrict__ m) {
    int c = blockIdx.x;
    int j = blockIdx.y * 256 + threadIdx.x;
    float Nj = (float)g_counts[c];
    g_mu[c * D + j] = (g_kap * m[j] + g_sums[c * D + j]) / (g_kap + Nj);
}

__global__ void k_lmat(const float* __restrict__ td, const float* __restrict__ tl) {
    int idx = blockIdx.x * 256 + threadIdx.x;
    int i = idx >> 10, j = idx & (D - 1);
    float v = (i == j) ? fabsf(td[i]) : (i > j ? tl[idx] : 0.f);
    g_Lm[idx] = v;
}

// base = Lm Lm^T + kap m m^T   (tiled 64x64, 4x4 micro)
__global__ __launch_bounds__(256) void k_base(const float* __restrict__ m) {
    __shared__ __align__(16) float As[16][68];
    __shared__ __align__(16) float Bs[16][68];
    int i0 = blockIdx.y * 64, j0 = blockIdx.x * 64;
    int tid = threadIdx.x, ty = tid >> 4, tx = tid & 15;
    float acc[4][4] = {};
    for (int k0 = 0; k0 < D; k0 += 16) {
        int r = tid >> 4, kk = tid & 15;
        #pragma unroll
        for (int it = 0; it < 4; it++) {
            As[kk][r + it * 16] = g_Lm[(size_t)(i0 + r + it * 16) * D + k0 + kk];
            Bs[kk][r + it * 16] = g_Lm[(size_t)(j0 + r + it * 16) * D + k0 + kk];
        }
        __syncthreads();
        #pragma unroll
        for (int q = 0; q < 16; q++) {
            float4 a = *(const float4*)&As[q][ty * 4];
            float4 b = *(const float4*)&Bs[q][tx * 4];
            float ar[4] = {a.x, a.y, a.z, a.w}, br[4] = {b.x, b.y, b.z, b.w};
            #pragma unroll
            for (int i = 0; i < 4; i++)
                #pragma unroll
                for (int j = 0; j < 4; j++) acc[i][j] += ar[i] * br[j];
        }
        __syncthreads();
    }
    float kap = g_kap;
    #pragma unroll
    for (int i = 0; i < 4; i++) {
        int gi = i0 + ty * 4 + i;
        #pragma unroll
        for (int j = 0; j < 4; j++) {
            int gj = j0 + tx * 4 + j;
            g_base[(size_t)gi * D + gj] = acc[i][j] + kap * m[gi] * m[gj];
        }
    }
}

__global__ void k_sigma_init() {
    size_t idx = (size_t)blockIdx.x * 256 + threadIdx.x;
    if (idx >= (size_t)CCLS * D * D) return;
    int c = (int)(idx / ((size_t)D * D));
    int rem = (int)(idx % ((size_t)D * D));
    int i = rem >> 10, j = rem & (D - 1);
    g_sigma[idx] = g_base[rem] - g_kapNj[c] * g_mu[c * D + i] * g_mu[c * D + j];
}

// S_c accumulate: sigma[c] += X_c^T X_c (gathered rows)
__global__ __launch_bounds__(256) void k_syrk(const float* __restrict__ X) {
    int c = blockIdx.z;
    int i0 = blockIdx.y * 64, j0 = blockIdx.x * 64;
    int o = g_offsets[c], cnt = g_offsets[c + 1] - o;
    __shared__ __align__(16) float As[16][68];
    __shared__ __align__(16) float Bs[16][68];
    __shared__ int pr[16];
    int tid = threadIdx.x, ty = tid >> 4, tx = tid & 15;
    float acc[4][4] = {};
    for (int k0 = 0; k0 < cnt; k0 += 16) {
        __syncthreads();
        if (tid < 16) pr[tid] = (k0 + tid < cnt) ? g_perm[o + k0 + tid] : -1;
        __syncthreads();
        int kk = tid >> 4;
        int row = pr[kk];
        #pragma unroll
        for (int it = 0; it < 4; it++) {
            int cc = (tid & 15) + it * 16;
            As[kk][cc] = (row >= 0) ? X[(size_t)row * D + i0 + cc] : 0.f;
            Bs[kk][cc] = (row >= 0) ? X[(size_t)row * D + j0 + cc] : 0.f;
        }
        __syncthreads();
        #pragma unroll
        for (int q = 0; q < 16; q++) {
            float4 a = *(const float4*)&As[q][ty * 4];
            float4 b = *(const float4*)&Bs[q][tx * 4];
            float ar[4] = {a.x, a.y, a.z, a.w}, br[4] = {b.x, b.y, b.z, b.w};
            #pragma unroll
            for (int i = 0; i < 4; i++)
                #pragma unroll
                for (int j = 0; j < 4; j++) acc[i][j] += ar[i] * br[j];
        }
    }
    float* Sg = g_sigma + (size_t)c * D * D;
    #pragma unroll
    for (int i = 0; i < 4; i++)
        #pragma unroll
        for (int j = 0; j < 4; j++)
            Sg[(size_t)(i0 + ty * 4 + i) * D + j0 + tx * 4 + j] += acc[i][j];
}

__global__ void k_scale() {
    size_t idx = (size_t)blockIdx.x * 256 + threadIdx.x;
    if (idx >= (size_t)CCLS * D * D) return;
    int c = (int)(idx / ((size_t)D * D));
    g_sigma[idx] *= g_invden[c];
}

// ---------------- blocked Cholesky ----------------
__global__ void k_chol_diag(int t) {
    int c = blockIdx.x;
    __shared__ float a[64][65];
    float* Sg = g_sigma + (size_t)c * D * D;
    int e = t * NB, ti = threadIdx.x;
    for (int x = ti; x < 4096; x += 64)
        a[x >> 6][x & 63] = Sg[(size_t)(e + (x >> 6)) * D + e + (x & 63)];
    __syncthreads();
    for (int j = 0; j < 64; j++) {
        if (ti == j) a[j][j] = sqrtf(a[j][j]);
        __syncthreads();
        float ljj = a[j][j];
        if (ti > j) a[ti][j] /= ljj;
        __syncthreads();
        if (ti > j) {
            float lij = a[ti][j];
            for (int k = j + 1; k <= ti; k++) a[ti][k] -= lij * a[k][j];
        }
        __syncthreads();
    }
    for (int x = ti; x < 4096; x += 64)
        Sg[(size_t)(e + (x >> 6)) * D + e + (x & 63)] = a[x >> 6][x & 63];
}

__global__ __launch_bounds__(128) void k_chol_panel(int t) {
    int c = blockIdx.x, e = t * NB;
    int row = e + NB + blockIdx.y * 128 + threadIdx.x;
    __shared__ float L11[64][65];
    float* Sg = g_sigma + (size_t)c * D * D;
    for (int x = threadIdx.x; x < 4096; x += 128)
        L11[x >> 6][x & 63] = Sg[(size_t)(e + (x >> 6)) * D + e + (x & 63)];
    __syncthreads();
    if (row < D) {
        float r[64];
        #pragma unroll
        for (int j = 0; j < 64; j++) r[j] = Sg[(size_t)row * D + e + j];
        #pragma unroll
        for (int j = 0; j < 64; j++) {
            float s = r[j];
            #pragma unroll
            for (int k = 0; k < j; k++) s -= r[k] * L11[j][k];
            r[j] = s / L11[j][j];
        }
        #pragma unroll
        for (int j = 0; j < 64; j++) Sg[(size_t)row * D + e + j] = r[j];
    }
}

__global__ __launch_bounds__(256) void k_chol_update(int t) {
    int c = blockIdx.z, e = t * NB, e2 = e + NB;
    int i0 = e2 + blockIdx.y * 64, j0 = e2 + blockIdx.x * 64;
    float* Sg = g_sigma + (size_t)c * D * D;
    __shared__ __align__(16) float As[64][68];
    __shared__ __align__(16) float Bs[64][68];
    int tid = threadIdx.x;
    int k = tid & 63, rb = tid >> 6;
    #pragma unroll
    for (int it = 0; it < 16; it++) {
        int r = rb + it * 4;
        As[k][r] = Sg[(size_t)(i0 + r) * D + e + k];
        Bs[k][r] = Sg[(size_t)(j0 + r) * D + e + k];
    }
    __syncthreads();
    int ty = tid >> 4, tx = tid & 15;
    float acc[4][4] = {};
    #pragma unroll 8
    for (int q = 0; q < 64; q++) {
        float4 a = *(const float4*)&As[q][ty * 4];
        float4 b = *(const float4*)&Bs[q][tx * 4];
        float ar[4] = {a.x, a.y, a.z, a.w}, br[4] = {b.x, b.y, b.z, b.w};
        #pragma unroll
        for (int i = 0; i < 4; i++)
            #pragma unroll
            for (int j = 0; j < 4; j++) acc[i][j] += ar[i] * br[j];
    }
    #pragma unroll
    for (int i = 0; i < 4; i++)
        #pragma unroll
        for (int j = 0; j < 4; j++)
            Sg[(size_t)(i0 + ty * 4 + i) * D + j0 + tx * 4 + j] -= acc[i][j];
}

// ---------------- triangular sweeps: W = inv(sigma) ----------------
__global__ void k_initW() {
    size_t idx = (size_t)blockIdx.x * 256 + threadIdx.x;
    if (idx >= (size_t)CCLS * D * D) return;
    int rem = (int)(idx % ((size_t)D * D));
    g_W[idx] = ((rem >> 10) == (rem & (D - 1))) ? 1.f : 0.f;
}

__global__ __launch_bounds__(64) void k_fsolve_diag(int t) {
    int c = blockIdx.y, e = t * NB;
    int col = blockIdx.x * 64 + threadIdx.x;
    __shared__ float L11[64][65];
    const float* Lg = g_sigma + (size_t)c * D * D;
    float* Wg = g_W + (size_t)c * D * D;
    for (int x = threadIdx.x; x < 4096; x += 64)
        L11[x >> 6][x & 63] = Lg[(size_t)(e + (x >> 6)) * D + e + (x & 63)];
    __syncthreads();
    float y[64];
    #pragma unroll
    for (int r = 0; r < 64; r++) {
        float s = Wg[(size_t)(e + r) * D + col];
        #pragma unroll
        for (int k = 0; k < r; k++) s -= L11[r][k] * y[k];
        y[r] = s / L11[r][r];
    }
    #pragma unroll
    for (int r = 0; r < 64; r++) Wg[(size_t)(e + r) * D + col] = y[r];
}

__global__ __launch_bounds__(256) void k_fupdate(int t) {
    int c = blockIdx.z, e = t * NB;
    int i0 = e + NB + blockIdx.y * 64, j0 = blockIdx.x * 64;
    const float* Lg = g_sigma + (size_t)c * D * D;
    float* Wg = g_W + (size_t)c * D * D;
    __shared__ __align__(16) float As[64][68];
    __shared__ __align__(16) float Bs[64][68];
    int tid = threadIdx.x;
    int k = tid & 63, rb = tid >> 6;
    #pragma unroll
    for (int it = 0; it < 16; it++) {
        int r = rb + it * 4;
        As[k][r] = Lg[(size_t)(i0 + r) * D + e + k];
        Bs[rb + it * 4][k] = Wg[(size_t)(e + rb + it * 4) * D + j0 + k];
    }
    __syncthreads();
    int ty = tid >> 4, tx = tid & 15;
    float acc[4][4] = {};
    #pragma unroll 8
    for (int q = 0; q < 64; q++) {
        float4 a = *(const float4*)&As[q][ty * 4];
        float4 b = *(const float4*)&Bs[q][tx * 4];
        float ar[4] = {a.x, a.y, a.z, a.w}, br[4] = {b.x, b.y, b.z, b.w};
        #pragma unroll
        for (int i = 0; i < 4; i++)
            #pragma unroll
            for (int j = 0; j < 4; j++) acc[i][j] += ar[i] * br[j];
    }
    #pragma unroll
    for (int i = 0; i < 4; i++)
        #pragma unroll
        for (int j = 0; j < 4; j++)
            Wg[(size_t)(i0 + ty * 4 + i) * D + j0 + tx * 4 + j] -= acc[i][j];
}

__global__ __launch_bounds__(64) void k_bsolve_diag(int t) {
    int c = blockIdx.y, e = t * NB;
    int col = blockIdx.x * 64 + threadIdx.x;
    __shared__ float L11[64][65];
    const float* Lg = g_sigma + (size_t)c * D * D;
    float* Wg = g_W + (size_t)c * D * D;
    for (int x = threadIdx.x; x < 4096; x += 64)
        L11[x >> 6][x & 63] = Lg[(size_t)(e + (x >> 6)) * D + e + (x & 63)];
    __syncthreads();
    float y[64];
    #pragma unroll
    for (int r = 63; r >= 0; r--) {
        float s = Wg[(size_t)(e + r) * D + col];
        #pragma unroll
        for (int k = r + 1; k < 64; k++) s -= L11[k][r] * y[k];
        y[r] = s / L11[r][r];
    }
    #pragma unroll
    for (int r = 0; r < 64; r++) Wg[(size_t)(e + r) * D + col] = y[r];
}

__global__ __launch_bounds__(256) void k_bupdate(int t) {
    int c = blockIdx.z, e = t * NB;
    int i0 = blockIdx.y * 64, j0 = blockIdx.x * 64;   // i0 < e
    const float* Lg = g_sigma + (size_t)c * D * D;
    float* Wg = g_W + (size_t)c * D * D;
    __shared__ __align__(16) float As[64][68];
    __shared__ __align__(16) float Bs[64][68];
    int tid = threadIdx.x;
    int k = tid & 63, rb = tid >> 6;
    #pragma unroll
    for (int it = 0; it < 16; it++) {
        int kr = rb + it * 4;
        As[kr][k] = Lg[(size_t)(e + kr) * D + i0 + k];  // A[k][r] = L[e+k][i0+r]
        Bs[kr][k] = Wg[(size_t)(e + kr) * D + j0 + k];
    }
    __syncthreads();
    int ty = tid >> 4, tx = tid & 15;
    float acc[4][4] = {};
    #pragma unroll 8
    for (int q = 0; q < 64; q++) {
        float4 a = *(const float4*)&As[q][ty * 4];
        float4 b = *(const float4*)&Bs[q][tx * 4];
        float ar[4] = {a.x, a.y, a.z, a.w}, br[4] = {b.x, b.y, b.z, b.w};
        #pragma unroll
        for (int i = 0; i < 4; i++)
            #pragma unroll
            for (int j = 0; j < 4; j++) acc[i][j] += ar[i] * br[j];
    }
    #pragma unroll
    for (int i = 0; i < 4; i++)
        #pragma unroll
        for (int j = 0; j < 4; j++)
            Wg[(size_t)(i0 + ty * 4 + i) * D + j0 + tx * 4 + j] -= acc[i][j];
}

// ---------------- predict ----------------
__global__ void k_vmu() {
    int c = blockIdx.x;
    const float* Wg = g_W + (size_t)c * D * D;
    const float* mu = g_mu + c * D;
    int lane = threadIdx.x & 31, w = threadIdx.x >> 5;
    for (int i = w; i < D; i += 8) {
        float s = 0.f;
        for (int j = lane; j < D; j += 32) s += Wg[(size_t)i * D + j] * mu[j];
        #pragma unroll
        for (int o = 16; o; o >>= 1) s += __shfl_xor_sync(0xffffffffu, s, o);
        if (lane == 0) g_v[c * D + i] = s;
    }
}

__global__ void k_s1() {
    int c = blockIdx.x;
    __shared__ float r1[256], r2[256];
    float s1 = 0.f, mn = 0.f;
    for (int i = threadIdx.x; i < D; i += 256) {
        float mv = g_mu[c * D + i];
        s1 += g_v[c * D + i] * mv;
        mn += mv * mv;
    }
    r1[threadIdx.x] = s1; r2[threadIdx.x] = mn;
    __syncthreads();
    for (int o = 128; o; o >>= 1) {
        if (threadIdx.x < o) { r1[threadIdx.x] += r1[threadIdx.x + o]; r2[threadIdx.x] += r2[threadIdx.x + o]; }
        __syncthreads();
    }
    if (threadIdx.x == 0) { g_s1[c] = r1[0]; g_mn[c] = r2[0]; }
}

__global__ void k_qn(const float* __restrict__ Xq, int M) {
    int w = blockIdx.x * 8 + (threadIdx.x >> 5);
    int lane = threadIdx.x & 31;
    if (w >= M) return;
    float s = 0.f;
    for (int j = lane; j < D; j += 32) { float v = Xq[(size_t)w * D + j]; s += v * v; }
    #pragma unroll
    for (int o = 16; o; o >>= 1) s += __shfl_xor_sync(0xffffffffu, s, o);
    if (lane == 0) g_qn[w] = s;
}

__global__ void k_dots(const float* __restrict__ Xq, int M) {
    int c = blockIdx.x;
    int m = blockIdx.y * 8 + (threadIdx.x >> 5);
    int lane = threadIdx.x & 31;
    if (m >= M) return;
    float s1 = 0.f, s2 = 0.f;
    for (int j = lane; j < D; j += 32) {
        float q = Xq[(size_t)m * D + j];
        s1 += q * g_v[c * D + j];
        s2 += q * g_mu[c * D + j];
    }
    #pragma unroll
    for (int o = 16; o; o >>= 1) {
        s1 += __shfl_xor_sync(0xffffffffu, s1, o);
        s2 += __shfl_xor_sync(0xffffffffu, s2, o);
    }
    if (lane == 0) { g_B1[m * CCLS + c] = s1; g_B2[m * CCLS + c] = s2; }
}

// A[m,c] = q_m^T W_c q_m  (fused GEMM + contraction, no G buffer)
__global__ __launch_bounds__(256) void k_quad(const float* __restrict__ Xq, int M) {
    int c = blockIdx.y, m0 = blockIdx.x * 64;
    const float* Wg = g_W + (size_t)c * D * D;
    __shared__ __align__(16) float Aq[16][68];
    __shared__ __align__(16) float Bw[16][68];
    __shared__ float red[64][17];
    int tid = threadIdx.x, ty = tid >> 4, tx = tid & 15;
    float pacc[4] = {0.f, 0.f, 0.f, 0.f};
    for (int j0 = 0; j0 < D; j0 += 64) {
        float acc[4][4] = {};
        for (int k0 = 0; k0 < D; k0 += 16) {
            int r = tid >> 4, kk = tid & 15;
            #pragma unroll
            for (int it = 0; it < 4; it++)
                Aq[kk][r + it * 16] = Xq[(size_t)(m0 + r + it * 16) * D + k0 + kk];
            int cc = tid & 63, kr = tid >> 6;
            #pragma unroll
            for (int it = 0; it < 4; it++)
                Bw[kr + it * 4][cc] = Wg[(size_t)(k0 + kr + it * 4) * D + j0 + cc];
            __syncthreads();
            #pragma unroll
            for (int q = 0; q < 16; q++) {
                float4 a = *(const float4*)&Aq[q][ty * 4];
                float4 b = *(const float4*)&Bw[q][tx * 4];
                float ar[4] = {a.x, a.y, a.z, a.w}, br[4] = {b.x, b.y, b.z, b.w};
                #pragma unroll
                for (int i = 0; i < 4; i++)
                    #pragma unroll
                    for (int j = 0; j < 4; j++) acc[i][j] += ar[i] * br[j];
            }
            __syncthreads();
        }
        #pragma unroll
        for (int i = 0; i < 4; i++)
            #pragma unroll
            for (int j = 0; j < 4; j++)
                pacc[i] += acc[i][j] * Xq[(size_t)(m0 + ty * 4 + i) * D + j0 + tx * 4 + j];
    }
    #pragma unroll
    for (int i = 0; i < 4; i++) red[ty * 4 + i][tx] = pacc[i];
    __syncthreads();
    if (tid < 64) {
        float s = 0.f;
        #pragma unroll
        for (int x = 0; x < 16; x++) s += red[tid][x];
        g_A[(size_t)(m0 + tid) * CCLS + c] = s;
    }
}

__global__ void k_combine(float* __restrict__ out, int M) {
    int idx = blockIdx.x * 256 + threadIdx.x;
    if (idx >= M * CCLS) return;
    int m = idx / CCLS, c = idx % CCLS;
    float quad = g_A[idx] - 2.f * g_B1[idx] + g_s1[c];
    float l2   = g_qn[m] - 2.f * g_B2[idx] + g_mn[c];
    out[idx] = -((1.f - REGC) * quad + REGC * l2);
}

// ---------------- launch ----------------
extern "C" void kernel_launch(void* const* d_in, const int* in_sizes, int n_in,
                              void* d_out, int out_size) {
    const float* X     = (const float*)d_in[0];
    const int*   y     = (const int*)  d_in[1];
    const float* Xq    = (const float*)d_in[2];
    const float* m     = (const float*)d_in[3];
    const float* kappa = (const float*)d_in[4];
    const float* nu    = (const float*)d_in[5];
    const float* td    = (const float*)d_in[6];
    const float* tl    = (const float*)d_in[7];
    float* out = (float*)d_out;
    int N = in_sizes[1];
    int M = in_sizes[2] / D;

    k_zero<<<1, CCLS>>>();
    k_count<<<(N + 255) / 256, 256>>>(y, N);
    k_prep<<<1, 1>>>(kappa, nu);
    k_scatter<<<(N + 255) / 256, 256>>>(y, N);
    k_sums<<<dim3(CCLS, D / 256), 256>>>(X);
    k_mu<<<dim3(CCLS, D / 256), 256>>>(m);
    k_lmat<<<D * D / 256, 256>>>(td, tl);
    k_base<<<dim3(D / 64, D / 64), 256>>>(m);
    k_sigma_init<<<(CCLS * D * D) / 256, 256>>>();
    k_syrk<<<dim3(D / 64, D / 64, CCLS), 256>>>(X);
    k_scale<<<(CCLS * D * D) / 256, 256>>>();

    for (int t = 0; t < TB; t++) {
        k_chol_diag<<<CCLS, 64>>>(t);
        int rows = D - (t + 1) * NB;
        if (rows > 0) {
            k_chol_panel<<<dim3(CCLS, (rows + 127) / 128), 128>>>(t);
            k_chol_update<<<dim3(rows / 64, rows / 64, CCLS), 256>>>(t);
        }
    }

    k_initW<<<(CCLS * D * D) / 256, 256>>>();
    for (int t = 0; t < TB; t++) {
        k_fsolve_diag<<<dim3(D / 64, CCLS), 64>>>(t);
        int rows = D - (t + 1) * NB;
        if (rows > 0) k_fupdate<<<dim3(D / 64, rows / 64, CCLS), 256>>>(t);
    }
    for (int t = TB - 1; t >= 0; t--) {
        k_bsolve_diag<<<dim3(D / 64, CCLS), 64>>>(t);
        if (t > 0) k_bupdate<<<dim3(D / 64, t, CCLS), 256>>>(t);
    }

    k_vmu<<<CCLS, 256>>>();
    k_s1<<<CCLS, 256>>>();
    k_qn<<<(M + 7) / 8, 256>>>(Xq, M);
    k_dots<<<dim3(CCLS, (M + 7) / 8), 256>>>(Xq, M);
    k_quad<<<dim3(M / 64, CCLS), 256>>>(Xq, M);
    k_combine<<<(M * CCLS + 255) / 256, 256>>>(out, M);
}

// round 2
// speedup vs baseline: 1.5312x; 1.5312x over previous
#include <cuda_runtime.h>
#include <math.h>

#define D 1024
#define CCLS 16
#define NB 64
#define TB (D/NB)
#define REGC 0.1f

// ---------------- scratch (device globals; no allocs allowed) ----------------
__device__ float g_sigma[(size_t)CCLS*D*D];   // sigma -> Cholesky L (lower)
__device__ float g_W[(size_t)CCLS*D*D];       // I -> L^-1 (lower triangular, upper zeros)
__device__ float g_Lm[(size_t)D*D];           // prior Cholesky factor
__device__ float g_base[(size_t)D*D];         // L L^T + kap m m^T
__device__ float g_mu[CCLS*D];
__device__ float g_sums[CCLS*D];
__device__ float g_t1[CCLS*D];                // Linv mu
__device__ float g_v[CCLS*D];                 // W mu = Linv^T t1
__device__ int   g_counts[CCLS];
__device__ int   g_offsets[CCLS+1];
__device__ int   g_perm[8192];
__device__ float g_kap;
__device__ float g_kapNj[CCLS];
__device__ float g_invden[CCLS];
__device__ float g_s1[CCLS], g_mn[CCLS];
__device__ float g_A[8192*CCLS], g_B1[8192*CCLS], g_B2[8192*CCLS], g_qn[8192];

// ---------------- stats ----------------
__global__ void k_zero() { if (threadIdx.x < CCLS) g_counts[threadIdx.x] = 0; }

__global__ void k_count(const int* __restrict__ y, int N) {
    int n = blockIdx.x * 256 + threadIdx.x;
    if (n < N) atomicAdd(&g_counts[y[n]], 1);
}

__global__ void k_prep(const float* __restrict__ kappa, const float* __restrict__ nu) {
    if (threadIdx.x == 0) {
        float kap = fabsf(kappa[0]) + 1e-6f;
        float nup = fmaxf(nu[0], (float)(D - 1) + 1e-6f);
        g_kap = kap;
        int off = 0;
        for (int c = 0; c < CCLS; c++) { g_offsets[c] = off; off += g_counts[c]; }
        g_offsets[CCLS] = off;
        for (int c = 0; c < CCLS; c++) {
            float Nj = (float)g_counts[c];
            g_kapNj[c]  = kap + Nj;
            g_invden[c] = 1.0f / (nup + Nj + (float)D + 2.0f);
        }
    }
}

// deterministic stable scatter: rank of n among same-class indices < n (y in smem)
__global__ __launch_bounds__(1024) void k_scatter(const int* __restrict__ y, int N) {
    __shared__ int ys[8192];
    for (int i = threadIdx.x; i < N; i += 1024) ys[i] = y[i];
    __syncthreads();
    for (int n = threadIdx.x; n < N; n += 1024) {
        int c = ys[n], r = 0;
        for (int i = 0; i < n; i++) r += (ys[i] == c);
        g_perm[g_offsets[c] + r] = n;
    }
}

__global__ void k_sums(const float* __restrict__ X) {
    int c = blockIdx.x;
    int j = blockIdx.y * 256 + threadIdx.x;
    int o = g_offsets[c], e = g_offsets[c + 1];
    float s = 0.f;
    for (int k = o; k < e; k++) s += X[(size_t)g_perm[k] * D + j];
    g_sums[c * D + j] = s;
}

__global__ void k_mu(const float* __restrict__ m) {
    int c = blockIdx.x;
    int j = blockIdx.y * 256 + threadIdx.x;
    float Nj = (float)g_counts[c];
    g_mu[c * D + j] = (g_kap * m[j] + g_sums[c * D + j]) / (g_kap + Nj);
}

__global__ void k_lmat(const float* __restrict__ td, const float* __restrict__ tl) {
    int idx = blockIdx.x * 256 + threadIdx.x;
    int i = idx >> 10, j = idx & (D - 1);
    float v = (i == j) ? fabsf(td[i]) : (i > j ? tl[idx] : 0.f);
    g_Lm[idx] = v;
}

// base = Lm Lm^T + kap m m^T   (tiled 64x64, 4x4 micro)
__global__ __launch_bounds__(256) void k_base(const float* __restrict__ m) {
    __shared__ __align__(16) float As[16][68];
    __shared__ __align__(16) float Bs[16][68];
    int i0 = blockIdx.y * 64, j0 = blockIdx.x * 64;
    int tid = threadIdx.x, ty = tid >> 4, tx = tid & 15;
    float acc[4][4] = {};
    for (int k0 = 0; k0 < D; k0 += 16) {
        int r = tid >> 4, kk = tid & 15;
        #pragma unroll
        for (int it = 0; it < 4; it++) {
            As[kk][r + it * 16] = g_Lm[(size_t)(i0 + r + it * 16) * D + k0 + kk];
            Bs[kk][r + it * 16] = g_Lm[(size_t)(j0 + r + it * 16) * D + k0 + kk];
        }
        __syncthreads();
        #pragma unroll
        for (int q = 0; q < 16; q++) {
            float4 a = *(const float4*)&As[q][ty * 4];
            float4 b = *(const float4*)&Bs[q][tx * 4];
            float ar[4] = {a.x, a.y, a.z, a.w}, br[4] = {b.x, b.y, b.z, b.w};
            #pragma unroll
            for (int i = 0; i < 4; i++)
                #pragma unroll
                for (int j = 0; j < 4; j++) acc[i][j] += ar[i] * br[j];
        }
        __syncthreads();
    }
    float kap = g_kap;
    #pragma unroll
    for (int i = 0; i < 4; i++) {
        int gi = i0 + ty * 4 + i;
        #pragma unroll
        for (int j = 0; j < 4; j++) {
            int gj = j0 + tx * 4 + j;
            g_base[(size_t)gi * D + gj] = acc[i][j] + kap * m[gi] * m[gj];
        }
    }
}

__global__ void k_sigma_init() {
    size_t idx = (size_t)blockIdx.x * 256 + threadIdx.x;
    if (idx >= (size_t)CCLS * D * D) return;
    int c = (int)(idx / ((size_t)D * D));
    int rem = (int)(idx % ((size_t)D * D));
    int i = rem >> 10, j = rem & (D - 1);
    g_sigma[idx] = g_base[rem] - g_kapNj[c] * g_mu[c * D + i] * g_mu[c * D + j];
}

// S_c accumulate: sigma[c] += X_c^T X_c (gathered rows), lower-triangle tiles only
__global__ __launch_bounds__(256) void k_syrk(const float* __restrict__ X) {
    if (blockIdx.y < blockIdx.x) return;  // only i0 >= j0 (Cholesky reads lower only)
    int c = blockIdx.z;
    int i0 = blockIdx.y * 64, j0 = blockIdx.x * 64;
    int o = g_offsets[c], cnt = g_offsets[c + 1] - o;
    __shared__ __align__(16) float As[16][68];
    __shared__ __align__(16) float Bs[16][68];
    __shared__ int pr[16];
    int tid = threadIdx.x, ty = tid >> 4, tx = tid & 15;
    float acc[4][4] = {};
    for (int k0 = 0; k0 < cnt; k0 += 16) {
        __syncthreads();
        if (tid < 16) pr[tid] = (k0 + tid < cnt) ? g_perm[o + k0 + tid] : -1;
        __syncthreads();
        int kk = tid >> 4;
        int row = pr[kk];
        #pragma unroll
        for (int it = 0; it < 4; it++) {
            int cc = (tid & 15) + it * 16;
            As[kk][cc] = (row >= 0) ? X[(size_t)row * D + i0 + cc] : 0.f;
            Bs[kk][cc] = (row >= 0) ? X[(size_t)row * D + j0 + cc] : 0.f;
        }
        __syncthreads();
        #pragma unroll
        for (int q = 0; q < 16; q++) {
            float4 a = *(const float4*)&As[q][ty * 4];
            float4 b = *(const float4*)&Bs[q][tx * 4];
            float ar[4] = {a.x, a.y, a.z, a.w}, br[4] = {b.x, b.y, b.z, b.w};
            #pragma unroll
            for (int i = 0; i < 4; i++)
                #pragma unroll
                for (int j = 0; j < 4; j++) acc[i][j] += ar[i] * br[j];
        }
    }
    float* Sg = g_sigma + (size_t)c * D * D;
    #pragma unroll
    for (int i = 0; i < 4; i++)
        #pragma unroll
        for (int j = 0; j < 4; j++)
            Sg[(size_t)(i0 + ty * 4 + i) * D + j0 + tx * 4 + j] += acc[i][j];
}

__global__ void k_scale() {
    size_t idx = (size_t)blockIdx.x * 256 + threadIdx.x;
    if (idx >= (size_t)CCLS * D * D) return;
    int c = (int)(idx / ((size_t)D * D));
    g_sigma[idx] *= g_invden[c];
}

// ---------------- blocked Cholesky ----------------
__global__ void k_chol_diag(int t) {
    int c = blockIdx.x;
    __shared__ float a[64][65];
    float* Sg = g_sigma + (size_t)c * D * D;
    int e = t * NB, ti = threadIdx.x;
    for (int x = ti; x < 4096; x += 64)
        a[x >> 6][x & 63] = Sg[(size_t)(e + (x >> 6)) * D + e + (x & 63)];
    __syncthreads();
    for (int j = 0; j < 64; j++) {
        if (ti == j) a[j][j] = sqrtf(a[j][j]);
        __syncthreads();
        float ljj = a[j][j];
        if (ti > j) a[ti][j] /= ljj;
        __syncthreads();
        if (ti > j) {
            float lij = a[ti][j];
            for (int k = j + 1; k <= ti; k++) a[ti][k] -= lij * a[k][j];
        }
        __syncthreads();
    }
    for (int x = ti; x < 4096; x += 64)
        Sg[(size_t)(e + (x >> 6)) * D + e + (x & 63)] = a[x >> 6][x & 63];
}

__global__ __launch_bounds__(128) void k_chol_panel(int t) {
    int c = blockIdx.x, e = t * NB;
    int row = e + NB + blockIdx.y * 128 + threadIdx.x;
    __shared__ float L11[64][65];
    float* Sg = g_sigma + (size_t)c * D * D;
    for (int x = threadIdx.x; x < 4096; x += 128)
        L11[x >> 6][x & 63] = Sg[(size_t)(e + (x >> 6)) * D + e + (x & 63)];
    __syncthreads();
    if (row < D) {
        float r[64];
        #pragma unroll
        for (int j = 0; j < 64; j++) r[j] = Sg[(size_t)row * D + e + j];
        #pragma unroll
        for (int j = 0; j < 64; j++) {
            float s = r[j];
            #pragma unroll
            for (int k = 0; k < j; k++) s -= r[k] * L11[j][k];
            r[j] = s / L11[j][j];
        }
        #pragma unroll
        for (int j = 0; j < 64; j++) Sg[(size_t)row * D + e + j] = r[j];
    }
}

__global__ __launch_bounds__(256) void k_chol_update(int t) {
    if (blockIdx.y < blockIdx.x) return;   // lower-triangle tiles only
    int c = blockIdx.z, e = t * NB, e2 = e + NB;
    int i0 = e2 + blockIdx.y * 64, j0 = e2 + blockIdx.x * 64;
    float* Sg = g_sigma + (size_t)c * D * D;
    __shared__ __align__(16) float As[64][68];
    __shared__ __align__(16) float Bs[64][68];
    int tid = threadIdx.x;
    int k = tid & 63, rb = tid >> 6;
    #pragma unroll
    for (int it = 0; it < 16; it++) {
        int r = rb + it * 4;
        As[k][r] = Sg[(size_t)(i0 + r) * D + e + k];
        Bs[k][r] = Sg[(size_t)(j0 + r) * D + e + k];
    }
    __syncthreads();
    int ty = tid >> 4, tx = tid & 15;
    float acc[4][4] = {};
    #pragma unroll 8
    for (int q = 0; q < 64; q++) {
        float4 a = *(const float4*)&As[q][ty * 4];
        float4 b = *(const float4*)&Bs[q][tx * 4];
        float ar[4] = {a.x, a.y, a.z, a.w}, br[4] = {b.x, b.y, b.z, b.w};
        #pragma unroll
        for (int i = 0; i < 4; i++)
            #pragma unroll
            for (int j = 0; j < 4; j++) acc[i][j] += ar[i] * br[j];
    }
    #pragma unroll
    for (int i = 0; i < 4; i++)
        #pragma unroll
        for (int j = 0; j < 4; j++)
            Sg[(size_t)(i0 + ty * 4 + i) * D + j0 + tx * 4 + j] -= acc[i][j];
}

// ---------------- forward sweep only: g_W = L^-1 (lower triangular) ----------------
__global__ void k_initW() {
    size_t idx = (size_t)blockIdx.x * 256 + threadIdx.x;
    if (idx >= (size_t)CCLS * D * D) return;
    int rem = (int)(idx % ((size_t)D * D));
    g_W[idx] = ((rem >> 10) == (rem & (D - 1))) ? 1.f : 0.f;
}

__global__ __launch_bounds__(64) void k_fsolve_diag(int t) {
    int c = blockIdx.y, e = t * NB;
    int col = blockIdx.x * 64 + threadIdx.x;   // grid.x = t+1: cols 0..e+63 only
    __shared__ float L11[64][65];
    const float* Lg = g_sigma + (size_t)c * D * D;
    float* Wg = g_W + (size_t)c * D * D;
    for (int x = threadIdx.x; x < 4096; x += 64)
        L11[x >> 6][x & 63] = Lg[(size_t)(e + (x >> 6)) * D + e + (x & 63)];
    __syncthreads();
    float y[64];
    #pragma unroll
    for (int r = 0; r < 64; r++) {
        float s = Wg[(size_t)(e + r) * D + col];
        #pragma unroll
        for (int k = 0; k < r; k++) s -= L11[r][k] * y[k];
        y[r] = s / L11[r][r];
    }
    #pragma unroll
    for (int r = 0; r < 64; r++) Wg[(size_t)(e + r) * D + col] = y[r];
}

__global__ __launch_bounds__(256) void k_fupdate(int t) {
    int c = blockIdx.z, e = t * NB;
    int i0 = e + NB + blockIdx.y * 64, j0 = blockIdx.x * 64;  // grid.x = t+1
    const float* Lg = g_sigma + (size_t)c * D * D;
    float* Wg = g_W + (size_t)c * D * D;
    __shared__ __align__(16) float As[64][68];
    __shared__ __align__(16) float Bs[64][68];
    int tid = threadIdx.x;
    int k = tid & 63, rb = tid >> 6;
    #pragma unroll
    for (int it = 0; it < 16; it++) {
        int r = rb + it * 4;
        As[k][r] = Lg[(size_t)(i0 + r) * D + e + k];
        Bs[rb + it * 4][k] = Wg[(size_t)(e + rb + it * 4) * D + j0 + k];
    }
    __syncthreads();
    int ty = tid >> 4, tx = tid & 15;
    float acc[4][4] = {};
    #pragma unroll 8
    for (int q = 0; q < 64; q++) {
        float4 a = *(const float4*)&As[q][ty * 4];
        float4 b = *(const float4*)&Bs[q][tx * 4];
        float ar[4] = {a.x, a.y, a.z, a.w}, br[4] = {b.x, b.y, b.z, b.w};
        #pragma unroll
        for (int i = 0; i < 4; i++)
            #pragma unroll
            for (int j = 0; j < 4; j++) acc[i][j] += ar[i] * br[j];
    }
    #pragma unroll
    for (int i = 0; i < 4; i++)
        #pragma unroll
        for (int j = 0; j < 4; j++)
            Wg[(size_t)(i0 + ty * 4 + i) * D + j0 + tx * 4 + j] -= acc[i][j];
}

// ---------------- predict helpers ----------------
// t1 = Linv * mu  (upper part of g_W is exactly zero, so full-row dot is safe)
__global__ void k_t1() {
    int c = blockIdx.x;
    const float* Lw = g_W + (size_t)c * D * D;
    const float* mu = g_mu + c * D;
    int lane = threadIdx.x & 31, w = threadIdx.x >> 5;
    for (int i = w; i < D; i += 8) {
        float s = 0.f;
        for (int j = lane; j <= i; j += 32) s += Lw[(size_t)i * D + j] * mu[j];
        #pragma unroll
        for (int o = 16; o; o >>= 1) s += __shfl_xor_sync(0xffffffffu, s, o);
        if (lane == 0) g_t1[c * D + i] = s;
    }
}

// v = Linv^T * t1 (coalesced row sweeps)
__global__ void k_v() {
    int c = blockIdx.x;
    int j = blockIdx.y * 256 + threadIdx.x;
    const float* Lw = g_W + (size_t)c * D * D;
    const float* t1 = g_t1 + c * D;
    float acc = 0.f;
    for (int i = j; i < D; i++) acc += Lw[(size_t)i * D + j] * t1[i];
    g_v[c * D + j] = acc;
}

__global__ void k_s1() {
    int c = blockIdx.x;
    __shared__ float r1[256], r2[256];
    float s1 = 0.f, mn = 0.f;
    for (int i = threadIdx.x; i < D; i += 256) {
        float t = g_t1[c * D + i];
        float mv = g_mu[c * D + i];
        s1 += t * t;
        mn += mv * mv;
    }
    r1[threadIdx.x] = s1; r2[threadIdx.x] = mn;
    __syncthreads();
    for (int o = 128; o; o >>= 1) {
        if (threadIdx.x < o) { r1[threadIdx.x] += r1[threadIdx.x + o]; r2[threadIdx.x] += r2[threadIdx.x + o]; }
        __syncthreads();
    }
    if (threadIdx.x == 0) { g_s1[c] = r1[0]; g_mn[c] = r2[0]; }
}

__global__ void k_qn(const float* __restrict__ Xq, int M) {
    int w = blockIdx.x * 8 + (threadIdx.x >> 5);
    int lane = threadIdx.x & 31;
    if (w >= M) return;
    float s = 0.f;
    for (int j = lane; j < D; j += 32) { float v = Xq[(size_t)w * D + j]; s += v * v; }
    #pragma unroll
    for (int o = 16; o; o >>= 1) s += __shfl_xor_sync(0xffffffffu, s, o);
    if (lane == 0) g_qn[w] = s;
}

__global__ void k_dots(const float* __restrict__ Xq, int M) {
    int c = blockIdx.x;
    int m = blockIdx.y * 8 + (threadIdx.x >> 5);
    int lane = threadIdx.x & 31;
    if (m >= M) return;
    float s1 = 0.f, s2 = 0.f;
    for (int j = lane; j < D; j += 32) {
        float q = Xq[(size_t)m * D + j];
        s1 += q * g_v[c * D + j];
        s2 += q * g_mu[c * D + j];
    }
    #pragma unroll
    for (int o = 16; o; o >>= 1) {
        s1 += __shfl_xor_sync(0xffffffffu, s1, o);
        s2 += __shfl_xor_sync(0xffffffffu, s2, o);
    }
    if (lane == 0) { g_B1[m * CCLS + c] = s1; g_B2[m * CCLS + c] = s2; }
}

// A[m,c] = || Linv_c q_m ||^2  (fused triangular matmul + square-accumulate)
__global__ __launch_bounds__(256) void k_trmm_norm(const float* __restrict__ Xq, int M) {
    int c = blockIdx.y, m0 = blockIdx.x * 64;
    const float* Lw = g_W + (size_t)c * D * D;
    __shared__ __align__(16) float Aq[16][68];  // [k][m]
    __shared__ __align__(16) float Bw[16][68];  // [k][i]
    __shared__ float red[64][17];
    int tid = threadIdx.x, ty = tid >> 4, tx = tid & 15;
    float pacc[4] = {0.f, 0.f, 0.f, 0.f};       // per m (m = tx*4 + j)
    for (int ib = 0; ib < 16; ib++) {
        int i0 = ib * 64;
        float acc[4][4] = {};                   // [i][m]
        for (int kb = 0; kb <= ib; kb++) {
            for (int kc = 0; kc < 64; kc += 16) {
                int kabs = kb * 64 + kc;
                int r = tid >> 4, kk = tid & 15;
                #pragma unroll
                for (int it = 0; it < 4; it++) {
                    Aq[kk][r + it * 16] = Xq[(size_t)(m0 + r + it * 16) * D + kabs + kk];
                    Bw[kk][r + it * 16] = Lw[(size_t)(i0 + r + it * 16) * D + kabs + kk];
                }
                __syncthreads();
                #pragma unroll
                for (int q = 0; q < 16; q++) {
                    float4 a = *(const float4*)&Bw[q][ty * 4];
                    float4 b = *(const float4*)&Aq[q][tx * 4];
                    float ar[4] = {a.x, a.y, a.z, a.w}, br[4] = {b.x, b.y, b.z, b.w};
                    #pragma unroll
                    for (int i = 0; i < 4; i++)
                        #pragma unroll
                        for (int j = 0; j < 4; j++) acc[i][j] += ar[i] * br[j];
                }
                __syncthreads();
            }
        }
        #pragma unroll
        for (int i = 0; i < 4; i++)
            #pragma unroll
            for (int j = 0; j < 4; j++) pacc[j] += acc[i][j] * acc[i][j];
    }
    #pragma unroll
    for (int j = 0; j < 4; j++) red[tx * 4 + j][ty] = pacc[j];
    __syncthreads();
    if (tid < 64) {
        float s = 0.f;
        #pragma unroll
        for (int x = 0; x < 16; x++) s += red[tid][x];
        g_A[(size_t)(m0 + tid) * CCLS + c] = s;
    }
}

__global__ void k_combine(float* __restrict__ out, int M) {
    int idx = blockIdx.x * 256 + threadIdx.x;
    if (idx >= M * CCLS) return;
    int m = idx / CCLS, c = idx % CCLS;
    float quad = g_A[idx] - 2.f * g_B1[idx] + g_s1[c];
    float l2   = g_qn[m] - 2.f * g_B2[idx] + g_mn[c];
    out[idx] = -((1.f - REGC) * quad + REGC * l2);
}

// ---------------- launch ----------------
extern "C" void kernel_launch(void* const* d_in, const int* in_sizes, int n_in,
                              void* d_out, int out_size) {
    const float* X     = (const float*)d_in[0];
    const int*   y     = (const int*)  d_in[1];
    const float* Xq    = (const float*)d_in[2];
    const float* m     = (const float*)d_in[3];
    const float* kappa = (const float*)d_in[4];
    const float* nu    = (const float*)d_in[5];
    const float* td    = (const float*)d_in[6];
    const float* tl    = (const float*)d_in[7];
    float* out = (float*)d_out;
    int N = in_sizes[1];
    int M = in_sizes[2] / D;

    k_zero<<<1, CCLS>>>();
    k_count<<<(N + 255) / 256, 256>>>(y, N);
    k_prep<<<1, 1>>>(kappa, nu);
    k_scatter<<<1, 1024>>>(y, N);
    k_sums<<<dim3(CCLS, D / 256), 256>>>(X);
    k_mu<<<dim3(CCLS, D / 256), 256>>>(m);
    k_lmat<<<D * D / 256, 256>>>(td, tl);
    k_base<<<dim3(D / 64, D / 64), 256>>>(m);
    k_sigma_init<<<(CCLS * D * D) / 256, 256>>>();
    k_syrk<<<dim3(D / 64, D / 64, CCLS), 256>>>(X);
    k_scale<<<(CCLS * D * D) / 256, 256>>>();

    for (int t = 0; t < TB; t++) {
        k_chol_diag<<<CCLS, 64>>>(t);
        int rows = D - (t + 1) * NB;
        if (rows > 0) {
            k_chol_panel<<<dim3(CCLS, (rows + 127) / 128), 128>>>(t);
            k_chol_update<<<dim3(rows / 64, rows / 64, CCLS), 256>>>(t);
        }
    }

    k_initW<<<(CCLS * D * D) / 256, 256>>>();
    for (int t = 0; t < TB; t++) {
        k_fsolve_diag<<<dim3(t + 1, CCLS), 64>>>(t);
        int rows = D - (t + 1) * NB;
        if (rows > 0) k_fupdate<<<dim3(t + 1, rows / 64, CCLS), 256>>>(t);
    }

    k_t1<<<CCLS, 256>>>();
    k_v<<<dim3(CCLS, D / 256), 256>>>();
    k_s1<<<CCLS, 256>>>();
    k_qn<<<(M + 7) / 8, 256>>>(Xq, M);
    k_dots<<<dim3(CCLS, (M + 7) / 8), 256>>>(Xq, M);
    k_trmm_norm<<<dim3(M / 64, CCLS), 256>>>(Xq, M);
    k_combine<<<(M * CCLS + 255) / 256, 256>>>(out, M);
}